// round 7
// baseline (speedup 1.0000x reference)
#include <cuda_runtime.h>
#include <cuda_bf16.h>
#include <cstdint>
#include <cstddef>

// Problem constants
#define BB 64
#define TT 2048
#define FF 128
#define UU 128
#define GG 512               // 4*U
#define MM (BB * TT)         // 131072 rows of x

// Scratch buffers (static __device__; allocation is forbidden)
__device__ float g_Z[2ull * 131072ull * 512ull];                 // z = x@Wx + b, both dirs
__device__ __align__(16) __nv_bfloat16 g_XH[131072ull * 128ull]; // x hi (bf16)
__device__ __align__(16) __nv_bfloat16 g_XL[131072ull * 128ull]; // x lo
__device__ __align__(16) __nv_bfloat16 g_WtH[2ull * 512ull * 128ull]; // W_x^T hi [dir][n][k]
__device__ __align__(16) __nv_bfloat16 g_WtL[2ull * 512ull * 128ull]; // W_x^T lo

// ---------------- f32x2 packed helpers ----------------
__device__ __forceinline__ unsigned long long fma2(unsigned long long a,
                                                   unsigned long long b,
                                                   unsigned long long c) {
    unsigned long long d;
    asm("fma.rn.f32x2 %0, %1, %2, %3;" : "=l"(d) : "l"(a), "l"(b), "l"(c));
    return d;
}
__device__ __forceinline__ unsigned long long pk(float x, float y) {
    unsigned long long d;
    asm("mov.b64 %0, {%1, %2};" : "=l"(d) : "f"(x), "f"(y));
    return d;
}
__device__ __forceinline__ float2 upk(unsigned long long a) {
    float2 r;
    asm("mov.b64 {%0, %1}, %2;" : "=f"(r.x), "=f"(r.y) : "l"(a));
    return r;
}

// ---------------- activations ----------------
__device__ __forceinline__ float sigm(float x) {
    return __fdividef(1.0f, 1.0f + __expf(-x));
}
__device__ __forceinline__ float tanh_fast(float x) {
    float ax = fabsf(x);
    float e  = __expf(-2.0f * ax);
    float r  = __fdividef(1.0f - e, 1.0f + e);
    return copysignf(r, x);
}

// ---------------- mma.sync helpers (no 'a'-target needed) ----------------
__device__ __forceinline__ uint32_t smem_u32(const void* p) {
    uint32_t a;
    asm("{ .reg .u64 t; cvta.to.shared.u64 t, %1; cvt.u32.u64 %0, t; }" : "=r"(a) : "l"(p));
    return a;
}
__device__ __forceinline__ void ldsm_x4(uint32_t addr, uint32_t* r) {
    asm volatile("ldmatrix.sync.aligned.m8n8.x4.shared.b16 {%0,%1,%2,%3}, [%4];"
                 : "=r"(r[0]), "=r"(r[1]), "=r"(r[2]), "=r"(r[3]) : "r"(addr));
}
__device__ __forceinline__ void mma_bf16(float* c, const uint32_t* a,
                                         uint32_t b0, uint32_t b1) {
    asm volatile("mma.sync.aligned.m16n8k16.row.col.f32.bf16.bf16.f32 "
                 "{%0,%1,%2,%3}, {%4,%5,%6,%7}, {%8,%9}, {%0,%1,%2,%3};"
                 : "+f"(c[0]), "+f"(c[1]), "+f"(c[2]), "+f"(c[3])
                 : "r"(a[0]), "r"(a[1]), "r"(a[2]), "r"(a[3]), "r"(b0), "r"(b1));
}

// =====================================================================
// Prep 1: x (fp32) -> XH, XL (bf16 split). 8 elems/thread.
// =====================================================================
__global__ __launch_bounds__(256) void convert_x(const float* __restrict__ x) {
    size_t i = ((size_t)blockIdx.x * 256 + threadIdx.x) * 8;
    float4 a = *(const float4*)(x + i);
    float4 b = *(const float4*)(x + i + 4);
    float f[8] = {a.x, a.y, a.z, a.w, b.x, b.y, b.z, b.w};
    union { __nv_bfloat16 h[8]; uint4 u; } H, L;
#pragma unroll
    for (int e = 0; e < 8; e++) {
        __nv_bfloat16 hi = __float2bfloat16(f[e]);
        H.h[e] = hi;
        L.h[e] = __float2bfloat16(f[e] - __bfloat162float(hi));
    }
    *(uint4*)(g_XH + i) = H.u;
    *(uint4*)(g_XL + i) = L.u;
}

// =====================================================================
// Prep 2: W_x (rows 0..127 of W) -> transposed bf16 split [dir][n][k]
// =====================================================================
__global__ __launch_bounds__(128) void transpose_w(const float* __restrict__ Wfw,
                                                   const float* __restrict__ Wbw) {
    int blk = blockIdx.x;
    int dir = blk >> 9;
    int n   = blk & 511;
    int k   = threadIdx.x;
    const float* W = dir ? Wbw : Wfw;
    float f = W[(size_t)k * GG + n];
    __nv_bfloat16 hi = __float2bfloat16(f);
    size_t o = ((size_t)dir * 512 + n) * 128 + k;
    g_WtH[o] = hi;
    g_WtL[o] = __float2bfloat16(f - __bfloat162float(hi));
}

// =====================================================================
// Phase 1: HMMA bf16-split GEMM (unchanged from R6 pass).
// grid (1024, 4, 2), block 256, smem 128 KB.
// =====================================================================
__global__ __launch_bounds__(256) void gemm_mma(const float* __restrict__ bfw,
                                                const float* __restrict__ bbw) {
    extern __shared__ unsigned char sm[];
    const int tid = threadIdx.x;
    const int m0 = blockIdx.x * 128;
    const int n0 = blockIdx.y * 128;
    const int dir = blockIdx.z;

#pragma unroll
    for (int buf = 0; buf < 2; buf++) {
        const __nv_bfloat16* A = buf ? g_XL : g_XH;
#pragma unroll
        for (int it = 0; it < 8; it++) {
            int task = it * 256 + tid;
            int r = task >> 4, u = task & 15;
            uint4 v = *(const uint4*)(A + (size_t)(m0 + r) * 128 + u * 8);
            int up = (u & 8) | ((u ^ r) & 7);
            *(uint4*)(sm + buf * 32768 + r * 256 + up * 16) = v;
        }
        const __nv_bfloat16* Bw = (buf ? g_WtL : g_WtH) + ((size_t)dir * 512 + n0) * 128;
#pragma unroll
        for (int it = 0; it < 8; it++) {
            int task = it * 256 + tid;
            int r = task >> 4, u = task & 15;
            uint4 v = *(const uint4*)(Bw + (size_t)r * 128 + u * 8);
            int up = (u & 8) | ((u ^ r) & 7);
            *(uint4*)(sm + 65536 + buf * 32768 + r * 256 + up * 16) = v;
        }
    }
    __syncthreads();

    const int w = tid >> 5, l = tid & 31;
    const int mb = (w & 3) * 32;
    const int nb = (w >> 2) * 64;
    const uint32_t sbase = smem_u32(sm);

    float c[2][8][4];
#pragma unroll
    for (int mi = 0; mi < 2; mi++)
#pragma unroll
        for (int ni = 0; ni < 8; ni++)
#pragma unroll
            for (int q = 0; q < 4; q++) c[mi][ni][q] = 0.0f;

    const int rAl = mb + (l & 15);
    const int hA  = l >> 4;
    const int rBl = nb + (l & 7) + ((l >> 4) << 3);
    const int hB  = (l >> 3) & 1;

#pragma unroll
    for (int p = 0; p < 3; p++) {
        const uint32_t Ab = sbase + (p == 2 ? 32768u : 0u);
        const uint32_t Bb = sbase + 65536u + (p == 1 ? 32768u : 0u);
#pragma unroll
        for (int kc = 0; kc < 8; kc++) {
            uint32_t a[2][4];
#pragma unroll
            for (int mi = 0; mi < 2; mi++) {
                int row = rAl + mi * 16;
                int u = kc * 2 + hA;
                uint32_t addr = Ab + row * 256 + ((u & 8) | ((u ^ row) & 7)) * 16;
                ldsm_x4(addr, a[mi]);
            }
            uint32_t b[4][4];
#pragma unroll
            for (int ni2 = 0; ni2 < 4; ni2++) {
                int row = rBl + ni2 * 16;
                int u = kc * 2 + hB;
                uint32_t addr = Bb + row * 256 + ((u & 8) | ((u ^ row) & 7)) * 16;
                ldsm_x4(addr, b[ni2]);
            }
#pragma unroll
            for (int mi = 0; mi < 2; mi++)
#pragma unroll
                for (int ni = 0; ni < 8; ni++)
                    mma_bf16(c[mi][ni], a[mi], b[ni >> 1][(ni & 1) * 2],
                             b[ni >> 1][(ni & 1) * 2 + 1]);
        }
    }

    const float* bias = dir ? bbw : bfw;
    const int gcol0 = n0 + nb + (l & 3) * 2;
    float2 bs[8];
#pragma unroll
    for (int ni = 0; ni < 8; ni++) bs[ni] = *(const float2*)(bias + gcol0 + ni * 8);

    float* Zb = g_Z + (size_t)dir * ((size_t)MM * GG);
    const int grow0 = m0 + mb + (l >> 2);
#pragma unroll
    for (int mi = 0; mi < 2; mi++) {
        float* r0 = Zb + (size_t)(grow0 + mi * 16) * GG;
        float* r1 = r0 + (size_t)8 * GG;
#pragma unroll
        for (int ni = 0; ni < 8; ni++) {
            float2 v0 = make_float2(c[mi][ni][0] + bs[ni].x, c[mi][ni][1] + bs[ni].y);
            float2 v1 = make_float2(c[mi][ni][2] + bs[ni].x, c[mi][ni][3] + bs[ni].y);
            *(float2*)(r0 + gcol0 + ni * 8) = v0;
            *(float2*)(r1 + gcol0 + ni * 8) = v1;
        }
    }
}

// =====================================================================
// Phase 2: persistent recurrence, row-split layout.
// 1 CTA per (batch, dir); 256 threads = 8 warps.
// Thread (w, l): unit u = w*16 + (l&15); half = l>>4 owns rows [half*64, half*64+64)
// of all 4 gate columns {u, 128+u, 256+u, 384+u}.
//   rows r0..r0+47 : registers (4 cols x 24 f32x2 = 192 regs)
//   rows r0+48..r0+63 : smem, layout [q2][half][u][gate pair] for LDS.128
// Partner l^16 holds the other row half; one shfl.xor(16) completes each gate sum.
// Single __syncthreads per step with double-buffered h.
// =====================================================================
#define RECTHR 256
#define RSP 24            // register pairs per column (48 rows per half)

__global__ __launch_bounds__(RECTHR) void lstm_rec(
    const float* __restrict__ Wfw,
    const float* __restrict__ Wbw,
    float* __restrict__ out) {
    const int tid  = threadIdx.x;
    const int w    = tid >> 5, l = tid & 31;
    const int half = l >> 4;
    const int u    = w * 16 + (l & 15);
    const int r0   = half * 64;
    const int dir = blockIdx.x & 1;
    const int b   = blockIdx.x >> 1;
    const float* W  = dir ? Wbw : Wfw;
    const float* Wh = W + FF * GG;       // rows 128..255 = W_h

    extern __shared__ unsigned char sraw[];
    // ws: q2 (0..3) x half (0..1) x u (0..127) x 4 u64 (gate-pairs g0..g3, two
    //     row-pairs per q2 interleaved as {pair 2q2 (g0..g3)=.x, pair 2q2+1=.y} via ulonglong2
    // layout: ws_u64[ ((q2*2+half)*128 + u)*8 + g*2 + pp ]   (pp = row-pair parity)
    unsigned long long* ws = (unsigned long long*)sraw;          // 4*2*128*8*8 = 65536 B
    float* hbf0 = (float*)(sraw + 65536);                        // 128 floats
    float* hbf1 = (float*)(sraw + 65536 + 512);                  // 128 floats

    const int cols[4] = {u, 128 + u, 256 + u, 384 + u};

    // ---- load weights: register part (rows r0 .. r0+47) ----
    unsigned long long wreg[4][RSP];
#pragma unroll
    for (int g = 0; g < 4; g++)
#pragma unroll
        for (int p = 0; p < RSP; p++)
            wreg[g][p] = pk(Wh[(size_t)(r0 + 2 * p) * GG + cols[g]],
                            Wh[(size_t)(r0 + 2 * p + 1) * GG + cols[g]]);
    // ---- smem part (rows r0+48 .. r0+63) ----
#pragma unroll
    for (int q2 = 0; q2 < 4; q2++) {
        int rr = r0 + 48 + 4 * q2;
        unsigned long long* base = ws + ((size_t)(q2 * 2 + half) * 128 + u) * 8;
#pragma unroll
        for (int g = 0; g < 4; g++) {
            base[g * 2 + 0] = pk(Wh[(size_t)(rr + 0) * GG + cols[g]],
                                 Wh[(size_t)(rr + 1) * GG + cols[g]]);
            base[g * 2 + 1] = pk(Wh[(size_t)(rr + 2) * GG + cols[g]],
                                 Wh[(size_t)(rr + 3) * GG + cols[g]]);
        }
    }
    if (tid < UU) hbf0[tid] = 0.0f;
    float c = 0.0f;
    __syncthreads();

    // ---- z stream (prefetch one step ahead) ----
    const size_t base = ((size_t)dir * MM + (size_t)b * TT) * GG;
    const float* zp;
    long long zstep;
    int tt0;
    if (dir == 0) { zp = g_Z + base;                          zstep =  GG; tt0 = 0; }
    else          { zp = g_Z + base + (size_t)(TT - 1) * GG;  zstep = -GG; tt0 = TT - 1; }
    float zn[4];
#pragma unroll
    for (int g = 0; g < 4; g++) zn[g] = zp[cols[g]];

    float* outp = out + ((size_t)b * TT + tt0) * (2 * UU) + dir * UU + u;  // lanes l<16 write
    const long long ostep = (dir == 0) ? (2 * UU) : -(2 * UU);

    int cur = 0;
    for (int t = 0; t < TT; t++) {
        float zc[4];
#pragma unroll
        for (int g = 0; g < 4; g++) zc[g] = zn[g];
        if (t + 1 < TT) {
            zp += zstep;
#pragma unroll
            for (int g = 0; g < 4; g++) zn[g] = zp[cols[g]];
        }

        const ulonglong2* hb2 =
            (const ulonglong2*)(cur ? hbf1 : hbf0) + half * 16;  // 16 entries (64 rows)

        unsigned long long accA[4] = {0ull, 0ull, 0ull, 0ull};
        unsigned long long accB[4] = {0ull, 0ull, 0ull, 0ull};
        // register rows: p = 0..11 (h rows r0+4p .. r0+4p+3)
#pragma unroll
        for (int p = 0; p < 12; p++) {
            ulonglong2 h2 = hb2[p];
#pragma unroll
            for (int g = 0; g < 4; g++) {
                accA[g] = fma2(wreg[g][2 * p], h2.x, accA[g]);
                accB[g] = fma2(wreg[g][2 * p + 1], h2.y, accB[g]);
            }
        }
        // smem rows: q2 = 0..3 (h rows r0+48+4q2 ..)
#pragma unroll
        for (int q2 = 0; q2 < 4; q2++) {
            ulonglong2 h2 = hb2[12 + q2];
            const ulonglong2* wb =
                (const ulonglong2*)(ws + ((size_t)(q2 * 2 + half) * 128 + u) * 8);
#pragma unroll
            for (int g = 0; g < 4; g++) {
                ulonglong2 wv = wb[g];
                accA[g] = fma2(wv.x, h2.x, accA[g]);
                accB[g] = fma2(wv.y, h2.y, accB[g]);
            }
        }

        float z[4];
#pragma unroll
        for (int g = 0; g < 4; g++) {
            float2 sA = upk(accA[g]), sB = upk(accB[g]);
            z[g] = (sA.x + sA.y) + (sB.x + sB.y);
        }
        // combine the two row-halves (partner lane l^16 has the same 4 columns)
#pragma unroll
        for (int g = 0; g < 4; g++)
            z[g] += __shfl_xor_sync(0xFFFFFFFFu, z[g], 16);
#pragma unroll
        for (int g = 0; g < 4; g++) z[g] += zc[g];

        float ai = sigm(z[0]);
        float aj = tanh_fast(z[1]);
        float af = sigm(z[2] + 1.0f);   // forget bias
        float ao = sigm(z[3]);
        c = fmaf(c, af, ai * aj);
        float h = ao * tanh_fast(c);

        float* hw = cur ? hbf0 : hbf1;   // write the other buffer
        if (l < 16) {
            hw[u] = h;
            *outp = h;
        }
        outp += ostep;
        cur ^= 1;
        __syncthreads();
    }
}

extern "C" void kernel_launch(void* const* d_in, const int* in_sizes, int n_in,
                              void* d_out, int out_size) {
    const float* x   = (const float*)d_in[0];
    const float* Wfw = (const float*)d_in[1];
    const float* bfw = (const float*)d_in[2];
    const float* Wbw = (const float*)d_in[3];
    const float* bbw = (const float*)d_in[4];
    float* out = (float*)d_out;

    cudaFuncSetAttribute(gemm_mma, cudaFuncAttributeMaxDynamicSharedMemorySize, 131072);
    const int recSmem = 65536 + 1024 + 256;  // ws + 2 x hbuf + pad
    cudaFuncSetAttribute(lstm_rec, cudaFuncAttributeMaxDynamicSharedMemorySize, recSmem);

    convert_x<<<8192, 256>>>(x);
    transpose_w<<<1024, 128>>>(Wfw, Wbw);
    dim3 gg(1024, 4, 2);
    gemm_mma<<<gg, 256, 131072>>>(bfw, bbw);
    lstm_rec<<<128, RECTHR, recSmem>>>(Wfw, Wbw, out);
}

// round 10
// speedup vs baseline: 1.3319x; 1.3319x over previous
#include <cuda_runtime.h>
#include <cuda_bf16.h>
#include <cstdint>
#include <cstddef>

// Problem constants
#define BB 64
#define TT 2048
#define FF 128
#define UU 128
#define GG 512               // 4*U
#define MM (BB * TT)         // 131072 rows of x

// Scratch buffers (static __device__; allocation is forbidden)
__device__ float g_Z[2ull * 131072ull * 512ull];                 // z = x@Wx + b, both dirs
__device__ __align__(16) __nv_bfloat16 g_XH[131072ull * 128ull]; // x hi (bf16)
__device__ __align__(16) __nv_bfloat16 g_XL[131072ull * 128ull]; // x lo
__device__ __align__(16) __nv_bfloat16 g_WtH[2ull * 512ull * 128ull]; // W_x^T hi [dir][n][k]
__device__ __align__(16) __nv_bfloat16 g_WtL[2ull * 512ull * 128ull]; // W_x^T lo

// ---------------- f32x2 packed helpers ----------------
__device__ __forceinline__ unsigned long long fma2(unsigned long long a,
                                                   unsigned long long b,
                                                   unsigned long long c) {
    unsigned long long d;
    asm("fma.rn.f32x2 %0, %1, %2, %3;" : "=l"(d) : "l"(a), "l"(b), "l"(c));
    return d;
}
__device__ __forceinline__ unsigned long long pk(float x, float y) {
    unsigned long long d;
    asm("mov.b64 %0, {%1, %2};" : "=l"(d) : "f"(x), "f"(y));
    return d;
}
__device__ __forceinline__ float2 upk(unsigned long long a) {
    float2 r;
    asm("mov.b64 {%0, %1}, %2;" : "=f"(r.x), "=f"(r.y) : "l"(a));
    return r;
}

// ---------------- activations ----------------
__device__ __forceinline__ float tanh_fast(float x) {
    float ax = fabsf(x);
    float e  = __expf(-2.0f * ax);
    float r  = __fdividef(1.0f - e, 1.0f + e);
    return copysignf(r, x);
}

// ---------------- mma.sync / cp.async helpers ----------------
__device__ __forceinline__ uint32_t smem_u32(const void* p) {
    uint32_t a;
    asm("{ .reg .u64 t; cvta.to.shared.u64 t, %1; cvt.u32.u64 %0, t; }" : "=r"(a) : "l"(p));
    return a;
}
__device__ __forceinline__ void ldsm_x4(uint32_t addr, uint32_t* r) {
    asm volatile("ldmatrix.sync.aligned.m8n8.x4.shared.b16 {%0,%1,%2,%3}, [%4];"
                 : "=r"(r[0]), "=r"(r[1]), "=r"(r[2]), "=r"(r[3]) : "r"(addr));
}
__device__ __forceinline__ void mma_bf16(float* c, const uint32_t* a,
                                         uint32_t b0, uint32_t b1) {
    asm volatile("mma.sync.aligned.m16n8k16.row.col.f32.bf16.bf16.f32 "
                 "{%0,%1,%2,%3}, {%4,%5,%6,%7}, {%8,%9}, {%0,%1,%2,%3};"
                 : "+f"(c[0]), "+f"(c[1]), "+f"(c[2]), "+f"(c[3])
                 : "r"(a[0]), "r"(a[1]), "r"(a[2]), "r"(a[3]), "r"(b0), "r"(b1));
}
#define CPA16(dst, src) \
    asm volatile("cp.async.cg.shared.global [%0], [%1], 16;" \
                 :: "r"(dst), "l"((const void*)(src)) : "memory")
#define CPA_COMMIT() asm volatile("cp.async.commit_group;" ::: "memory")
#define CPA_WAIT(n)  asm volatile("cp.async.wait_group %0;" :: "n"(n) : "memory")

// =====================================================================
// Prep 1: x (fp32) -> XH, XL (bf16 split). 8 elems/thread.
// =====================================================================
__global__ __launch_bounds__(256) void convert_x(const float* __restrict__ x) {
    size_t i = ((size_t)blockIdx.x * 256 + threadIdx.x) * 8;
    float4 a = *(const float4*)(x + i);
    float4 b = *(const float4*)(x + i + 4);
    float f[8] = {a.x, a.y, a.z, a.w, b.x, b.y, b.z, b.w};
    union { __nv_bfloat16 h[8]; uint4 u; } H, L;
#pragma unroll
    for (int e = 0; e < 8; e++) {
        __nv_bfloat16 hi = __float2bfloat16(f[e]);
        H.h[e] = hi;
        L.h[e] = __float2bfloat16(f[e] - __bfloat162float(hi));
    }
    *(uint4*)(g_XH + i) = H.u;
    *(uint4*)(g_XL + i) = L.u;
}

// =====================================================================
// Prep 2: W_x (rows 0..127 of W) -> transposed bf16 split [dir][n][k]
// =====================================================================
__global__ __launch_bounds__(128) void transpose_w(const float* __restrict__ Wfw,
                                                   const float* __restrict__ Wbw) {
    int blk = blockIdx.x;
    int dir = blk >> 9;
    int n   = blk & 511;
    int k   = threadIdx.x;
    const float* W = dir ? Wbw : Wfw;
    float f = W[(size_t)k * GG + n];
    __nv_bfloat16 hi = __float2bfloat16(f);
    size_t o = ((size_t)dir * 512 + n) * 128 + k;
    g_WtH[o] = hi;
    g_WtL[o] = __float2bfloat16(f - __bfloat162float(hi));
}

// =====================================================================
// Phase 1: HMMA bf16-split GEMM with cp.async staged loads.
// Pass order: AH*BH (wait g1), AL*BH (wait g2), AH*BL (wait g3).
// grid (1024, 4, 2), block 256, smem 128 KB.
// smem: AH@0 AL@32768 BH@65536 BL@98304  (128 rows x 256 B, swizzled)
// =====================================================================
__global__ __launch_bounds__(256) void gemm_mma(const float* __restrict__ bfw,
                                                const float* __restrict__ bbw) {
    extern __shared__ unsigned char sm[];
    const int tid = threadIdx.x;
    const int m0 = blockIdx.x * 128;
    const int n0 = blockIdx.y * 128;
    const int dir = blockIdx.z;
    const uint32_t sbase = smem_u32(sm);

    const __nv_bfloat16* BwH = g_WtH + ((size_t)dir * 512 + n0) * 128;
    const __nv_bfloat16* BwL = g_WtL + ((size_t)dir * 512 + n0) * 128;

    // group 1: AH + BH
#pragma unroll
    for (int it = 0; it < 8; it++) {
        int task = it * 256 + tid;
        int r = task >> 4, uq = task & 15;
        int up = (uq & 8) | ((uq ^ r) & 7);
        CPA16(sbase + r * 256 + up * 16, g_XH + (size_t)(m0 + r) * 128 + uq * 8);
    }
#pragma unroll
    for (int it = 0; it < 8; it++) {
        int task = it * 256 + tid;
        int r = task >> 4, uq = task & 15;
        int up = (uq & 8) | ((uq ^ r) & 7);
        CPA16(sbase + 65536 + r * 256 + up * 16, BwH + (size_t)r * 128 + uq * 8);
    }
    CPA_COMMIT();
    // group 2: AL
#pragma unroll
    for (int it = 0; it < 8; it++) {
        int task = it * 256 + tid;
        int r = task >> 4, uq = task & 15;
        int up = (uq & 8) | ((uq ^ r) & 7);
        CPA16(sbase + 32768 + r * 256 + up * 16, g_XL + (size_t)(m0 + r) * 128 + uq * 8);
    }
    CPA_COMMIT();
    // group 3: BL
#pragma unroll
    for (int it = 0; it < 8; it++) {
        int task = it * 256 + tid;
        int r = task >> 4, uq = task & 15;
        int up = (uq & 8) | ((uq ^ r) & 7);
        CPA16(sbase + 98304 + r * 256 + up * 16, BwL + (size_t)r * 128 + uq * 8);
    }
    CPA_COMMIT();

    const int w = tid >> 5, l = tid & 31;
    const int mb = (w & 3) * 32;
    const int nb = (w >> 2) * 64;

    float c[2][8][4];
#pragma unroll
    for (int mi = 0; mi < 2; mi++)
#pragma unroll
        for (int ni = 0; ni < 8; ni++)
#pragma unroll
            for (int q = 0; q < 4; q++) c[mi][ni][q] = 0.0f;

    const int rAl = mb + (l & 15);
    const int hA  = l >> 4;
    const int rBl = nb + (l & 7) + ((l >> 4) << 3);
    const int hB  = (l >> 3) & 1;

#pragma unroll
    for (int p = 0; p < 3; p++) {
        if (p == 0)      { CPA_WAIT(2); }
        else if (p == 1) { CPA_WAIT(1); }
        else             { CPA_WAIT(0); }
        __syncthreads();
        // p0: AH*BH, p1: AL*BH, p2: AH*BL
        const uint32_t Ab = sbase + (p == 1 ? 32768u : 0u);
        const uint32_t Bb = sbase + 65536u + (p == 2 ? 32768u : 0u);
#pragma unroll
        for (int kc = 0; kc < 8; kc++) {
            uint32_t a[2][4];
#pragma unroll
            for (int mi = 0; mi < 2; mi++) {
                int row = rAl + mi * 16;
                int u = kc * 2 + hA;
                uint32_t addr = Ab + row * 256 + ((u & 8) | ((u ^ row) & 7)) * 16;
                ldsm_x4(addr, a[mi]);
            }
            uint32_t b[4][4];
#pragma unroll
            for (int ni2 = 0; ni2 < 4; ni2++) {
                int row = rBl + ni2 * 16;
                int u = kc * 2 + hB;
                uint32_t addr = Bb + row * 256 + ((u & 8) | ((u ^ row) & 7)) * 16;
                ldsm_x4(addr, b[ni2]);
            }
#pragma unroll
            for (int mi = 0; mi < 2; mi++)
#pragma unroll
                for (int ni = 0; ni < 8; ni++)
                    mma_bf16(c[mi][ni], a[mi], b[ni >> 1][(ni & 1) * 2],
                             b[ni >> 1][(ni & 1) * 2 + 1]);
        }
    }

    const float* bias = dir ? bbw : bfw;
    const int gcol0 = n0 + nb + (l & 3) * 2;
    float2 bs[8];
#pragma unroll
    for (int ni = 0; ni < 8; ni++) bs[ni] = *(const float2*)(bias + gcol0 + ni * 8);

    float* Zb = g_Z + (size_t)dir * ((size_t)MM * GG);
    const int grow0 = m0 + mb + (l >> 2);
#pragma unroll
    for (int mi = 0; mi < 2; mi++) {
        float* r0 = Zb + (size_t)(grow0 + mi * 16) * GG;
        float* r1 = r0 + (size_t)8 * GG;
#pragma unroll
        for (int ni = 0; ni < 8; ni++) {
            float2 v0 = make_float2(c[mi][ni][0] + bs[ni].x, c[mi][ni][1] + bs[ni].y);
            float2 v1 = make_float2(c[mi][ni][2] + bs[ni].x, c[mi][ni][3] + bs[ni].y);
            *(float2*)(r0 + gcol0 + ni * 8) = v0;
            *(float2*)(r1 + gcol0 + ni * 8) = v1;
        }
    }
}

// =====================================================================
// Phase 2: persistent recurrence. R2 weight split + same-warp gate pairing.
// 256 threads; warp w, lane l: lo = l&15, hs = l>>4, unit u = w*16+lo.
//   hs=0: cols u (gate i), u+256 (gate f)
//   hs=1: cols u+128 (gate j), u+384 (gate o)
// Rows 0..99 in registers (2 cols x 50 pairs = 200 regs);
// rows 100..127 in smem (7 ulonglong2 blocks x 512 cols = 57344 B).
// Activate own gates (tanh identity, divergence-free), shfl.xor(16) the
// activated pair, replicate c/h in both lanes. ONE barrier per step,
// double-buffered h.
// =====================================================================
#define RECTHR 256
#define SMBLK  7
#define RPAIR  50

__global__ __launch_bounds__(RECTHR) void lstm_rec(
    const float* __restrict__ Wfw,
    const float* __restrict__ Wbw,
    float* __restrict__ out) {
    const int tid = threadIdx.x;
    const int w   = tid >> 5, l = tid & 31;
    const int lo  = l & 15, hs = l >> 4;
    const int u   = w * 16 + lo;
    const int cA  = u + hs * 128;        // gate i (hs=0) or j (hs=1)
    const int cB  = cA + 256;            // gate f (hs=0) or o (hs=1)
    const int dir = blockIdx.x & 1;
    const int b   = blockIdx.x >> 1;
    const float* W  = dir ? Wbw : Wfw;
    const float* Wh = W + FF * GG;       // rows 128..255 = W_h

    extern __shared__ unsigned char sraw[];
    ulonglong2* ws = (ulonglong2*)sraw;                    // 7*512*16 = 57344 B
    float* hbf0 = (float*)(sraw + SMBLK * 512 * 16);       // 128 floats
    float* hbf1 = (float*)(sraw + SMBLK * 512 * 16 + 512); // 128 floats

    // ---- load weights ----
    unsigned long long w0[2 * RPAIR];   // column cA: pairs 0..49 (rows 0..99)
    unsigned long long w1[2 * RPAIR];   // column cB
#pragma unroll
    for (int p = 0; p < RPAIR; p++) {
        w0[p] = pk(Wh[(size_t)(2 * p) * GG + cA], Wh[(size_t)(2 * p + 1) * GG + cA]);
        w1[p] = pk(Wh[(size_t)(2 * p) * GG + cB], Wh[(size_t)(2 * p + 1) * GG + cB]);
    }
#pragma unroll
    for (int q = 0; q < SMBLK; q++) {
        int rr = 100 + 4 * q;
        ulonglong2 vA, vB;
        vA.x = pk(Wh[(size_t)(rr + 0) * GG + cA], Wh[(size_t)(rr + 1) * GG + cA]);
        vA.y = pk(Wh[(size_t)(rr + 2) * GG + cA], Wh[(size_t)(rr + 3) * GG + cA]);
        vB.x = pk(Wh[(size_t)(rr + 0) * GG + cB], Wh[(size_t)(rr + 1) * GG + cB]);
        vB.y = pk(Wh[(size_t)(rr + 2) * GG + cB], Wh[(size_t)(rr + 3) * GG + cB]);
        ws[q * 512 + cA] = vA;
        ws[q * 512 + cB] = vB;
    }
    if (tid < UU) hbf0[tid] = 0.0f;
    float c = 0.0f;
    __syncthreads();

    // ---- z stream (prefetch one step ahead) ----
    const size_t base = ((size_t)dir * MM + (size_t)b * TT) * GG;
    const float* zp;
    long long zstep;
    int tt0;
    if (dir == 0) { zp = g_Z + base;                          zstep =  GG; tt0 = 0; }
    else          { zp = g_Z + base + (size_t)(TT - 1) * GG;  zstep = -GG; tt0 = TT - 1; }
    float znA = zp[cA], znB = zp[cB];

    float* outp = out + ((size_t)b * TT + tt0) * (2 * UU) + dir * UU + u;  // hs==0 writes
    const long long ostep = (dir == 0) ? (2 * UU) : -(2 * UU);

    // lane-constant activation params:
    // hs=0: actA = sigm(zA)   = 0.5*tanh(0.5*zA) + 0.5
    // hs=1: actA = tanh(zA)   = 1.0*tanh(1.0*zA) + 0.0
    // actB = sigm(zB + fb)    (fb = 1 for hs=0 forget gate, 0 for hs=1 output gate)
    const float kA = hs ? 1.0f : 0.5f;
    const float aA = hs ? 1.0f : 0.5f;
    const float bA = hs ? 0.0f : 0.5f;
    const float fb = hs ? 0.0f : 1.0f;

    int cur = 0;
    for (int t = 0; t < TT; t++) {
        float zcA = znA, zcB = znB;
        if (t + 1 < TT) { zp += zstep; znA = zp[cA]; znB = zp[cB]; }

        const ulonglong2* hb2 = (const ulonglong2*)(cur ? hbf1 : hbf0);
        unsigned long long a00 = 0ull, a01 = 0ull, a10 = 0ull, a11 = 0ull;
#pragma unroll
        for (int p = 0; p < 25; p++) {                   // rows 0..99 (registers)
            ulonglong2 h2 = hb2[p];
            a00 = fma2(w0[2 * p], h2.x, a00);
            a01 = fma2(w0[2 * p + 1], h2.y, a01);
            a10 = fma2(w1[2 * p], h2.x, a10);
            a11 = fma2(w1[2 * p + 1], h2.y, a11);
        }
#pragma unroll
        for (int q = 0; q < SMBLK; q++) {                // rows 100..127 (smem)
            ulonglong2 h2 = hb2[25 + q];
            ulonglong2 wA = ws[q * 512 + cA];
            ulonglong2 wB = ws[q * 512 + cB];
            a00 = fma2(wA.x, h2.x, a00);
            a01 = fma2(wA.y, h2.y, a01);
            a10 = fma2(wB.x, h2.x, a10);
            a11 = fma2(wB.y, h2.y, a11);
        }
        float2 s0 = upk(a00), s1 = upk(a01);
        float2 s2 = upk(a10), s3 = upk(a11);
        float zA = (s0.x + s0.y) + (s1.x + s1.y) + zcA;
        float zB = (s2.x + s2.y) + (s3.x + s3.y) + zcB;

        // activate own two gates (uniform instruction stream, lane-varying params)
        float actA = fmaf(aA, tanh_fast(kA * zA), bA);
        float actB = fmaf(0.5f, tanh_fast(0.5f * (zB + fb)), 0.5f);

        // exchange activated gates with partner lane (l ^ 16)
        float pA = __shfl_xor_sync(0xFFFFFFFFu, actA, 16);
        float pB = __shfl_xor_sync(0xFFFFFFFFu, actB, 16);
        float gi = hs ? pA : actA;    // input gate (sigm)
        float gj = hs ? actA : pA;    // candidate (tanh)
        float gf = hs ? pB : actB;    // forget gate (sigm, +1 bias)
        float go = hs ? actB : pB;    // output gate (sigm)

        c = fmaf(c, gf, gi * gj);
        float h = go * tanh_fast(c);

        float* hw = cur ? hbf0 : hbf1;    // write the other buffer
        if (hs == 0) {
            hw[u] = h;
            *outp = h;
        }
        outp += ostep;
        cur ^= 1;
        __syncthreads();
    }
}

extern "C" void kernel_launch(void* const* d_in, const int* in_sizes, int n_in,
                              void* d_out, int out_size) {
    const float* x   = (const float*)d_in[0];
    const float* Wfw = (const float*)d_in[1];
    const float* bfw = (const float*)d_in[2];
    const float* Wbw = (const float*)d_in[3];
    const float* bbw = (const float*)d_in[4];
    float* out = (float*)d_out;

    cudaFuncSetAttribute(gemm_mma, cudaFuncAttributeMaxDynamicSharedMemorySize, 131072);
    const int recSmem = SMBLK * 512 * 16 + 1024 + 256;  // ws + 2 hbufs + pad
    cudaFuncSetAttribute(lstm_rec, cudaFuncAttributeMaxDynamicSharedMemorySize, recSmem);

    convert_x<<<8192, 256>>>(x);
    transpose_w<<<1024, 128>>>(Wfw, Wbw);
    dim3 gg(1024, 4, 2);
    gemm_mma<<<gg, 256, 131072>>>(bfw, bbw);
    lstm_rec<<<128, RECTHR, recSmem>>>(Wfw, Wbw, out);
}

// round 11
// speedup vs baseline: 1.8388x; 1.3806x over previous
#include <cuda_runtime.h>
#include <cuda_bf16.h>
#include <cstdint>
#include <cstddef>

// Problem constants
#define BB 64
#define TT 2048
#define FF 128
#define UU 128
#define GG 512               // 4*U
#define MM (BB * TT)         // 131072 rows of x

// Scratch buffers (static __device__; allocation is forbidden)
__device__ float g_Z[2ull * 131072ull * 512ull];                 // z = x@Wx + b, both dirs
__device__ __align__(16) __nv_bfloat16 g_XH[131072ull * 128ull]; // x hi (bf16)
__device__ __align__(16) __nv_bfloat16 g_XL[131072ull * 128ull]; // x lo
__device__ __align__(16) __nv_bfloat16 g_WtH[2ull * 512ull * 128ull]; // W_x^T hi [dir][n][k]
__device__ __align__(16) __nv_bfloat16 g_WtL[2ull * 512ull * 128ull]; // W_x^T lo

// ---------------- f32x2 packed helpers ----------------
__device__ __forceinline__ unsigned long long fma2(unsigned long long a,
                                                   unsigned long long b,
                                                   unsigned long long c) {
    unsigned long long d;
    asm("fma.rn.f32x2 %0, %1, %2, %3;" : "=l"(d) : "l"(a), "l"(b), "l"(c));
    return d;
}
__device__ __forceinline__ unsigned long long pk(float x, float y) {
    unsigned long long d;
    asm("mov.b64 %0, {%1, %2};" : "=l"(d) : "f"(x), "f"(y));
    return d;
}
__device__ __forceinline__ float2 upk(unsigned long long a) {
    float2 r;
    asm("mov.b64 {%0, %1}, %2;" : "=f"(r.x), "=f"(r.y) : "l"(a));
    return r;
}

// ---------------- activations (HW tanh unit) ----------------
__device__ __forceinline__ float tanhA(float x) {
    float y;
    asm("tanh.approx.f32 %0, %1;" : "=f"(y) : "f"(x));
    return y;
}
__device__ __forceinline__ float sigmA(float x) {
    return fmaf(0.5f, tanhA(0.5f * x), 0.5f);
}

// ---------------- mma.sync / cp.async helpers ----------------
__device__ __forceinline__ uint32_t smem_u32(const void* p) {
    uint32_t a;
    asm("{ .reg .u64 t; cvta.to.shared.u64 t, %1; cvt.u32.u64 %0, t; }" : "=r"(a) : "l"(p));
    return a;
}
__device__ __forceinline__ void ldsm_x4(uint32_t addr, uint32_t* r) {
    asm volatile("ldmatrix.sync.aligned.m8n8.x4.shared.b16 {%0,%1,%2,%3}, [%4];"
                 : "=r"(r[0]), "=r"(r[1]), "=r"(r[2]), "=r"(r[3]) : "r"(addr));
}
__device__ __forceinline__ void mma_bf16(float* c, const uint32_t* a,
                                         uint32_t b0, uint32_t b1) {
    asm volatile("mma.sync.aligned.m16n8k16.row.col.f32.bf16.bf16.f32 "
                 "{%0,%1,%2,%3}, {%4,%5,%6,%7}, {%8,%9}, {%0,%1,%2,%3};"
                 : "+f"(c[0]), "+f"(c[1]), "+f"(c[2]), "+f"(c[3])
                 : "r"(a[0]), "r"(a[1]), "r"(a[2]), "r"(a[3]), "r"(b0), "r"(b1));
}
#define CPA16(dst, src) \
    asm volatile("cp.async.cg.shared.global [%0], [%1], 16;" \
                 :: "r"(dst), "l"((const void*)(src)) : "memory")
#define CPA_COMMIT() asm volatile("cp.async.commit_group;" ::: "memory")
#define CPA_WAIT(n)  asm volatile("cp.async.wait_group %0;" :: "n"(n) : "memory")

// =====================================================================
// Prep 1: x (fp32) -> XH, XL (bf16 split). 8 elems/thread.
// =====================================================================
__global__ __launch_bounds__(256) void convert_x(const float* __restrict__ x) {
    size_t i = ((size_t)blockIdx.x * 256 + threadIdx.x) * 8;
    float4 a = *(const float4*)(x + i);
    float4 b = *(const float4*)(x + i + 4);
    float f[8] = {a.x, a.y, a.z, a.w, b.x, b.y, b.z, b.w};
    union { __nv_bfloat16 h[8]; uint4 u; } H, L;
#pragma unroll
    for (int e = 0; e < 8; e++) {
        __nv_bfloat16 hi = __float2bfloat16(f[e]);
        H.h[e] = hi;
        L.h[e] = __float2bfloat16(f[e] - __bfloat162float(hi));
    }
    *(uint4*)(g_XH + i) = H.u;
    *(uint4*)(g_XL + i) = L.u;
}

// =====================================================================
// Prep 2: W_x (rows 0..127 of W) -> transposed bf16 split [dir][n][k]
// =====================================================================
__global__ __launch_bounds__(128) void transpose_w(const float* __restrict__ Wfw,
                                                   const float* __restrict__ Wbw) {
    int blk = blockIdx.x;
    int dir = blk >> 9;
    int n   = blk & 511;
    int k   = threadIdx.x;
    const float* W = dir ? Wbw : Wfw;
    float f = W[(size_t)k * GG + n];
    __nv_bfloat16 hi = __float2bfloat16(f);
    size_t o = ((size_t)dir * 512 + n) * 128 + k;
    g_WtH[o] = hi;
    g_WtL[o] = __float2bfloat16(f - __bfloat162float(hi));
}

// =====================================================================
// Phase 1: HMMA bf16-split GEMM with cp.async staged loads (R10, kept).
// Pass order: AH*BH (wait g1), AL*BH (wait g2), AH*BL (wait g3).
// grid (1024, 4, 2), block 256, smem 128 KB.
// =====================================================================
__global__ __launch_bounds__(256) void gemm_mma(const float* __restrict__ bfw,
                                                const float* __restrict__ bbw) {
    extern __shared__ unsigned char sm[];
    const int tid = threadIdx.x;
    const int m0 = blockIdx.x * 128;
    const int n0 = blockIdx.y * 128;
    const int dir = blockIdx.z;
    const uint32_t sbase = smem_u32(sm);

    const __nv_bfloat16* BwH = g_WtH + ((size_t)dir * 512 + n0) * 128;
    const __nv_bfloat16* BwL = g_WtL + ((size_t)dir * 512 + n0) * 128;

    // group 1: AH + BH
#pragma unroll
    for (int it = 0; it < 8; it++) {
        int task = it * 256 + tid;
        int r = task >> 4, uq = task & 15;
        int up = (uq & 8) | ((uq ^ r) & 7);
        CPA16(sbase + r * 256 + up * 16, g_XH + (size_t)(m0 + r) * 128 + uq * 8);
    }
#pragma unroll
    for (int it = 0; it < 8; it++) {
        int task = it * 256 + tid;
        int r = task >> 4, uq = task & 15;
        int up = (uq & 8) | ((uq ^ r) & 7);
        CPA16(sbase + 65536 + r * 256 + up * 16, BwH + (size_t)r * 128 + uq * 8);
    }
    CPA_COMMIT();
    // group 2: AL
#pragma unroll
    for (int it = 0; it < 8; it++) {
        int task = it * 256 + tid;
        int r = task >> 4, uq = task & 15;
        int up = (uq & 8) | ((uq ^ r) & 7);
        CPA16(sbase + 32768 + r * 256 + up * 16, g_XL + (size_t)(m0 + r) * 128 + uq * 8);
    }
    CPA_COMMIT();
    // group 3: BL
#pragma unroll
    for (int it = 0; it < 8; it++) {
        int task = it * 256 + tid;
        int r = task >> 4, uq = task & 15;
        int up = (uq & 8) | ((uq ^ r) & 7);
        CPA16(sbase + 98304 + r * 256 + up * 16, BwL + (size_t)r * 128 + uq * 8);
    }
    CPA_COMMIT();

    const int w = tid >> 5, l = tid & 31;
    const int mb = (w & 3) * 32;
    const int nb = (w >> 2) * 64;

    float c[2][8][4];
#pragma unroll
    for (int mi = 0; mi < 2; mi++)
#pragma unroll
        for (int ni = 0; ni < 8; ni++)
#pragma unroll
            for (int q = 0; q < 4; q++) c[mi][ni][q] = 0.0f;

    const int rAl = mb + (l & 15);
    const int hA  = l >> 4;
    const int rBl = nb + (l & 7) + ((l >> 4) << 3);
    const int hB  = (l >> 3) & 1;

#pragma unroll
    for (int p = 0; p < 3; p++) {
        if (p == 0)      { CPA_WAIT(2); }
        else if (p == 1) { CPA_WAIT(1); }
        else             { CPA_WAIT(0); }
        __syncthreads();
        // p0: AH*BH, p1: AL*BH, p2: AH*BL
        const uint32_t Ab = sbase + (p == 1 ? 32768u : 0u);
        const uint32_t Bb = sbase + 65536u + (p == 2 ? 32768u : 0u);
#pragma unroll
        for (int kc = 0; kc < 8; kc++) {
            uint32_t a[2][4];
#pragma unroll
            for (int mi = 0; mi < 2; mi++) {
                int row = rAl + mi * 16;
                int u = kc * 2 + hA;
                uint32_t addr = Ab + row * 256 + ((u & 8) | ((u ^ row) & 7)) * 16;
                ldsm_x4(addr, a[mi]);
            }
            uint32_t b[4][4];
#pragma unroll
            for (int ni2 = 0; ni2 < 4; ni2++) {
                int row = rBl + ni2 * 16;
                int u = kc * 2 + hB;
                uint32_t addr = Bb + row * 256 + ((u & 8) | ((u ^ row) & 7)) * 16;
                ldsm_x4(addr, b[ni2]);
            }
#pragma unroll
            for (int mi = 0; mi < 2; mi++)
#pragma unroll
                for (int ni = 0; ni < 8; ni++)
                    mma_bf16(c[mi][ni], a[mi], b[ni >> 1][(ni & 1) * 2],
                             b[ni >> 1][(ni & 1) * 2 + 1]);
        }
    }

    const float* bias = dir ? bbw : bfw;
    const int gcol0 = n0 + nb + (l & 3) * 2;
    float2 bs[8];
#pragma unroll
    for (int ni = 0; ni < 8; ni++) bs[ni] = *(const float2*)(bias + gcol0 + ni * 8);

    float* Zb = g_Z + (size_t)dir * ((size_t)MM * GG);
    const int grow0 = m0 + mb + (l >> 2);
#pragma unroll
    for (int mi = 0; mi < 2; mi++) {
        float* r0 = Zb + (size_t)(grow0 + mi * 16) * GG;
        float* r1 = r0 + (size_t)8 * GG;
#pragma unroll
        for (int ni = 0; ni < 8; ni++) {
            float2 v0 = make_float2(c[mi][ni][0] + bs[ni].x, c[mi][ni][1] + bs[ni].y);
            float2 v1 = make_float2(c[mi][ni][2] + bs[ni].x, c[mi][ni][3] + bs[ni].y);
            *(float2*)(r0 + gcol0 + ni * 8) = v0;
            *(float2*)(r1 + gcol0 + ni * 8) = v1;
        }
    }
}

// =====================================================================
// Phase 2: persistent recurrence — EXACT R2/R6 structure (best measured),
// with hardware tanh.approx activations (the single change this round).
// 256 threads, thread t owns gate-columns t and t+256:
//   rows 0..99   -> 50 packed f32x2 register pairs per column (200 regs)
//   rows 100..127-> 14 pairs per column in smem as ulonglong2 blocks
// grid = 128, block = 256
// =====================================================================
#define RECTHR 256
#define SMBLK  7
#define RPAIR  50

__global__ __launch_bounds__(RECTHR) void lstm_rec(
    const float* __restrict__ Wfw,
    const float* __restrict__ Wbw,
    float* __restrict__ out) {
    const int tid = threadIdx.x;
    const int j0  = tid;             // gate column A
    const int j1  = tid + 256;       // gate column B
    const int dir = blockIdx.x & 1;
    const int b   = blockIdx.x >> 1;
    const float* W  = dir ? Wbw : Wfw;
    const float* Wh = W + FF * GG;   // rows 128..255 = W_h

    extern __shared__ unsigned char sraw[];
    ulonglong2* ws = (ulonglong2*)sraw;                         // 7*512*16 = 57344 B
    float* zs   = (float*)(sraw + SMBLK * 512 * 16);            // 512 floats
    float* hbuf = (float*)(sraw + SMBLK * 512 * 16 + 2048);     // 128 floats, 16B aligned

    // ---- load weights ----
    unsigned long long w0[2 * RPAIR];   // column j0: pairs 0..49
    unsigned long long w1[2 * RPAIR];   // column j1
#pragma unroll
    for (int p = 0; p < RPAIR; p++) {
        w0[p] = pk(Wh[(size_t)(2 * p) * GG + j0], Wh[(size_t)(2 * p + 1) * GG + j0]);
        w1[p] = pk(Wh[(size_t)(2 * p) * GG + j1], Wh[(size_t)(2 * p + 1) * GG + j1]);
    }
#pragma unroll
    for (int q = 0; q < SMBLK; q++) {
        int r = 100 + 4 * q;
        ulonglong2 vA, vB;
        vA.x = pk(Wh[(size_t)(r + 0) * GG + j0], Wh[(size_t)(r + 1) * GG + j0]);
        vA.y = pk(Wh[(size_t)(r + 2) * GG + j0], Wh[(size_t)(r + 3) * GG + j0]);
        vB.x = pk(Wh[(size_t)(r + 0) * GG + j1], Wh[(size_t)(r + 1) * GG + j1]);
        vB.y = pk(Wh[(size_t)(r + 2) * GG + j1], Wh[(size_t)(r + 3) * GG + j1]);
        ws[q * 512 + j0] = vA;
        ws[q * 512 + j1] = vB;
    }
    if (tid < UU) hbuf[tid] = 0.0f;
    float c = 0.0f;
    __syncthreads();

    // ---- z stream (prefetch one step ahead) ----
    const size_t base = ((size_t)dir * MM + (size_t)b * TT) * GG;
    const float* zp;
    long long zstep;
    int tt0;
    if (dir == 0) { zp = g_Z + base;                          zstep =  GG; tt0 = 0; }
    else          { zp = g_Z + base + (size_t)(TT - 1) * GG;  zstep = -GG; tt0 = TT - 1; }
    float zn0 = zp[j0], zn1 = zp[j1];

    float* outp = out + ((size_t)b * TT + tt0) * (2 * UU) + dir * UU + tid; // valid iff tid<128
    const long long ostep = (dir == 0) ? (2 * UU) : -(2 * UU);
    const int q4 = tid & 127;

    for (int t = 0; t < TT; t++) {
        float zc0 = zn0, zc1 = zn1;
        if (t + 1 < TT) { zp += zstep; zn0 = zp[j0]; zn1 = zp[j1]; }

        const ulonglong2* hb = (const ulonglong2*)hbuf;  // hb[p] = h pairs (2p, 2p+1)
        unsigned long long a00 = 0ull, a01 = 0ull, a10 = 0ull, a11 = 0ull;
#pragma unroll
        for (int p = 0; p < 25; p++) {                   // rows 0..99 (registers)
            ulonglong2 h2 = hb[p];
            a00 = fma2(w0[2 * p], h2.x, a00);
            a01 = fma2(w0[2 * p + 1], h2.y, a01);
            a10 = fma2(w1[2 * p], h2.x, a10);
            a11 = fma2(w1[2 * p + 1], h2.y, a11);
        }
#pragma unroll
        for (int qq = 0; qq < SMBLK; qq++) {             // rows 100..127 (smem)
            ulonglong2 h2 = hb[25 + qq];
            ulonglong2 wA = ws[qq * 512 + j0];
            ulonglong2 wB = ws[qq * 512 + j1];
            a00 = fma2(wA.x, h2.x, a00);
            a01 = fma2(wA.y, h2.y, a01);
            a10 = fma2(wB.x, h2.x, a10);
            a11 = fma2(wB.y, h2.y, a11);
        }
        float2 s0 = upk(a00), s1 = upk(a01);
        float2 s2 = upk(a10), s3 = upk(a11);
        float z0 = (s0.x + s0.y) + (s1.x + s1.y) + zc0;
        float z1 = (s2.x + s2.y) + (s3.x + s3.y) + zc1;

        // col j0: gate 0 (i, sigm) or 1 (j, tanh); col j1: gate 2 (f, sigm+1) or 3 (o, sigm)
        float act0, act1;
        if (tid < 128) { act0 = sigmA(z0);  act1 = sigmA(z1 + 1.0f); }
        else           { act0 = tanhA(z0);  act1 = sigmA(z1); }
        zs[j0] = act0;
        zs[j1] = act1;
        __syncthreads();

        // c/h update replicated in threads q4 and q4+128 (identical arithmetic)
        float ai = zs[q4], aj = zs[q4 + 128], af = zs[q4 + 256], ao = zs[q4 + 384];
        c = fmaf(c, af, ai * aj);
        float h = ao * tanhA(c);
        if (tid < UU) {
            hbuf[tid] = h;
            *outp = h;
            outp += ostep;
        }
        __syncthreads();
    }
}

extern "C" void kernel_launch(void* const* d_in, const int* in_sizes, int n_in,
                              void* d_out, int out_size) {
    const float* x   = (const float*)d_in[0];
    const float* Wfw = (const float*)d_in[1];
    const float* bfw = (const float*)d_in[2];
    const float* Wbw = (const float*)d_in[3];
    const float* bbw = (const float*)d_in[4];
    float* out = (float*)d_out;

    cudaFuncSetAttribute(gemm_mma, cudaFuncAttributeMaxDynamicSharedMemorySize, 131072);
    const int recSmem = SMBLK * 512 * 16 + 2048 + 512;  // 59904
    cudaFuncSetAttribute(lstm_rec, cudaFuncAttributeMaxDynamicSharedMemorySize, recSmem);

    convert_x<<<8192, 256>>>(x);
    transpose_w<<<1024, 128>>>(Wfw, Wbw);
    dim3 gg(1024, 4, 2);
    gemm_mma<<<gg, 256, 131072>>>(bfw, bbw);
    lstm_rec<<<128, RECTHR, recSmem>>>(Wfw, Wbw, out);
}

// round 12
// speedup vs baseline: 1.8665x; 1.0151x over previous
#include <cuda_runtime.h>
#include <cuda_bf16.h>
#include <cstdint>
#include <cstddef>

// Problem constants
#define BB 64
#define TT 2048
#define FF 128
#define UU 128
#define GG 512               // 4*U
#define MM (BB * TT)         // 131072 rows of x

// Scratch buffers (static __device__; allocation is forbidden)
__device__ float g_Z[2ull * 131072ull * 512ull];                 // z = x@Wx + b, both dirs
__device__ __align__(16) __nv_bfloat16 g_XH[131072ull * 128ull]; // x hi (bf16)
__device__ __align__(16) __nv_bfloat16 g_XL[131072ull * 128ull]; // x lo
__device__ __align__(16) __nv_bfloat16 g_WtH[2ull * 512ull * 128ull]; // W_x^T hi [dir][n][k]
__device__ __align__(16) __nv_bfloat16 g_WtL[2ull * 512ull * 128ull]; // W_x^T lo

// ---------------- f32x2 packed helpers ----------------
__device__ __forceinline__ unsigned long long fma2(unsigned long long a,
                                                   unsigned long long b,
                                                   unsigned long long c) {
    unsigned long long d;
    asm("fma.rn.f32x2 %0, %1, %2, %3;" : "=l"(d) : "l"(a), "l"(b), "l"(c));
    return d;
}
__device__ __forceinline__ unsigned long long pk(float x, float y) {
    unsigned long long d;
    asm("mov.b64 %0, {%1, %2};" : "=l"(d) : "f"(x), "f"(y));
    return d;
}
__device__ __forceinline__ float2 upk(unsigned long long a) {
    float2 r;
    asm("mov.b64 {%0, %1}, %2;" : "=f"(r.x), "=f"(r.y) : "l"(a));
    return r;
}

// ---------------- activations (HW tanh unit) ----------------
__device__ __forceinline__ float tanhA(float x) {
    float y;
    asm("tanh.approx.f32 %0, %1;" : "=f"(y) : "f"(x));
    return y;
}
__device__ __forceinline__ float sigmA(float x) {
    return fmaf(0.5f, tanhA(0.5f * x), 0.5f);
}

// ---------------- mma.sync / cp.async helpers ----------------
__device__ __forceinline__ uint32_t smem_u32(const void* p) {
    uint32_t a;
    asm("{ .reg .u64 t; cvta.to.shared.u64 t, %1; cvt.u32.u64 %0, t; }" : "=r"(a) : "l"(p));
    return a;
}
__device__ __forceinline__ void ldsm_x4(uint32_t addr, uint32_t* r) {
    asm volatile("ldmatrix.sync.aligned.m8n8.x4.shared.b16 {%0,%1,%2,%3}, [%4];"
                 : "=r"(r[0]), "=r"(r[1]), "=r"(r[2]), "=r"(r[3]) : "r"(addr));
}
__device__ __forceinline__ void mma_bf16(float* c, const uint32_t* a,
                                         uint32_t b0, uint32_t b1) {
    asm volatile("mma.sync.aligned.m16n8k16.row.col.f32.bf16.bf16.f32 "
                 "{%0,%1,%2,%3}, {%4,%5,%6,%7}, {%8,%9}, {%0,%1,%2,%3};"
                 : "+f"(c[0]), "+f"(c[1]), "+f"(c[2]), "+f"(c[3])
                 : "r"(a[0]), "r"(a[1]), "r"(a[2]), "r"(a[3]), "r"(b0), "r"(b1));
}
#define CPA16(dst, src) \
    asm volatile("cp.async.cg.shared.global [%0], [%1], 16;" \
                 :: "r"(dst), "l"((const void*)(src)) : "memory")
#define CPA_COMMIT() asm volatile("cp.async.commit_group;" ::: "memory")
#define CPA_WAIT(n)  asm volatile("cp.async.wait_group %0;" :: "n"(n) : "memory")

// =====================================================================
// Prep 1: x (fp32) -> XH, XL (bf16 split). 8 elems/thread.
// =====================================================================
__global__ __launch_bounds__(256) void convert_x(const float* __restrict__ x) {
    size_t i = ((size_t)blockIdx.x * 256 + threadIdx.x) * 8;
    float4 a = *(const float4*)(x + i);
    float4 b = *(const float4*)(x + i + 4);
    float f[8] = {a.x, a.y, a.z, a.w, b.x, b.y, b.z, b.w};
    union { __nv_bfloat16 h[8]; uint4 u; } H, L;
#pragma unroll
    for (int e = 0; e < 8; e++) {
        __nv_bfloat16 hi = __float2bfloat16(f[e]);
        H.h[e] = hi;
        L.h[e] = __float2bfloat16(f[e] - __bfloat162float(hi));
    }
    *(uint4*)(g_XH + i) = H.u;
    *(uint4*)(g_XL + i) = L.u;
}

// =====================================================================
// Prep 2: W_x (rows 0..127 of W) -> transposed bf16 split [dir][n][k]
// =====================================================================
__global__ __launch_bounds__(128) void transpose_w(const float* __restrict__ Wfw,
                                                   const float* __restrict__ Wbw) {
    int blk = blockIdx.x;
    int dir = blk >> 9;
    int n   = blk & 511;
    int k   = threadIdx.x;
    const float* W = dir ? Wbw : Wfw;
    float f = W[(size_t)k * GG + n];
    __nv_bfloat16 hi = __float2bfloat16(f);
    size_t o = ((size_t)dir * 512 + n) * 128 + k;
    g_WtH[o] = hi;
    g_WtL[o] = __float2bfloat16(f - __bfloat162float(hi));
}

// =====================================================================
// Phase 1: persistent HMMA bf16-split GEMM with double-buffered A stream.
// grid (18, 4, 2) = 144 CTAs (one wave). Each CTA owns (n0, dir):
//   - loads BH+BL (64 KB) ONCE, resident
//   - streams m-tiles job = bx, bx+18, ... < 1024 with cp.async double buffer
// smem: BH@0(32K) BL@32768(32K) A[2]: AH@65536/AL@98304, AH@131072/AL@163840
// Total 192 KB.
// =====================================================================
#define GMX 18
__global__ __launch_bounds__(256) void gemm_mma(const float* __restrict__ bfw,
                                                const float* __restrict__ bbw) {
    extern __shared__ unsigned char sm[];
    const int tid = threadIdx.x;
    const int n0 = blockIdx.y * 128;
    const int dir = blockIdx.z;
    const uint32_t sbase = smem_u32(sm);

    const __nv_bfloat16* BwH = g_WtH + ((size_t)dir * 512 + n0) * 128;
    const __nv_bfloat16* BwL = g_WtL + ((size_t)dir * 512 + n0) * 128;

    // per-thread load indices (128 rows x 16 units / 256 threads = 8 each)
    // thread covers rows r = tid>>4 + 16*it, unit uq = tid&15
    const int lr = tid >> 4, uq = tid & 15;
    const int up = (uq & 8) | ((uq ^ lr) & 7);   // NOTE: swizzle depends on row!
    // swizzle depends on row, recompute per row below.

    // ---- B tiles (resident) ----
#pragma unroll
    for (int it = 0; it < 8; it++) {
        int r = lr + 16 * it;
        int u2 = (uq & 8) | ((uq ^ r) & 7);
        CPA16(sbase + r * 256 + u2 * 16, BwH + (size_t)r * 128 + uq * 8);
        CPA16(sbase + 32768 + r * 256 + u2 * 16, BwL + (size_t)r * 128 + uq * 8);
    }
    CPA_COMMIT();

    int job = blockIdx.x;
    // ---- prologue: A tile for first job into buffer 0 ----
    {
        const size_t a0 = (size_t)job * 128 * 128;
#pragma unroll
        for (int it = 0; it < 8; it++) {
            int r = lr + 16 * it;
            int u2 = (uq & 8) | ((uq ^ r) & 7);
            CPA16(sbase + 65536 + r * 256 + u2 * 16, g_XH + a0 + (size_t)r * 128 + uq * 8);
            CPA16(sbase + 98304 + r * 256 + u2 * 16, g_XL + a0 + (size_t)r * 128 + uq * 8);
        }
        CPA_COMMIT();
    }
    CPA_WAIT(0);
    __syncthreads();

    const int w = tid >> 5, l = tid & 31;
    const int mb = (w & 3) * 32;
    const int nb = (w >> 2) * 64;

    const int rAl = mb + (l & 15);
    const int hA  = l >> 4;
    const int rBl = nb + (l & 7) + ((l >> 4) << 3);
    const int hB  = (l >> 3) & 1;

    const float* bias = dir ? bbw : bfw;
    const int gcol0 = n0 + nb + (l & 3) * 2;
    float2 bs[8];
#pragma unroll
    for (int ni = 0; ni < 8; ni++) bs[ni] = *(const float2*)(bias + gcol0 + ni * 8);
    float* Zb = g_Z + (size_t)dir * ((size_t)MM * GG);

    int cb = 0;
    while (job < 1024) {
        const int nxt = job + GMX;
        if (nxt < 1024) {
            // issue next A tile into the other buffer
            const size_t a0 = (size_t)nxt * 128 * 128;
            const uint32_t ab = sbase + 65536u + (cb ^ 1) * 65536u;
#pragma unroll
            for (int it = 0; it < 8; it++) {
                int r = lr + 16 * it;
                int u2 = (uq & 8) | ((uq ^ r) & 7);
                CPA16(ab + r * 256 + u2 * 16, g_XH + a0 + (size_t)r * 128 + uq * 8);
                CPA16(ab + 32768 + r * 256 + u2 * 16, g_XL + a0 + (size_t)r * 128 + uq * 8);
            }
            CPA_COMMIT();
            CPA_WAIT(1);   // current buffer's group (older) must be complete
        } else {
            CPA_WAIT(0);
        }
        __syncthreads();

        float c[2][8][4];
#pragma unroll
        for (int mi = 0; mi < 2; mi++)
#pragma unroll
            for (int ni = 0; ni < 8; ni++)
#pragma unroll
                for (int q = 0; q < 4; q++) c[mi][ni][q] = 0.0f;

        const uint32_t Abase = sbase + 65536u + cb * 65536u;
#pragma unroll
        for (int p = 0; p < 3; p++) {
            // p0: AH*BH, p1: AL*BH, p2: AH*BL
            const uint32_t Ab = Abase + (p == 1 ? 32768u : 0u);
            const uint32_t Bb = sbase + (p == 2 ? 32768u : 0u);
#pragma unroll
            for (int kc = 0; kc < 8; kc++) {
                uint32_t a[2][4];
#pragma unroll
                for (int mi = 0; mi < 2; mi++) {
                    int row = rAl + mi * 16;
                    int u = kc * 2 + hA;
                    uint32_t addr = Ab + row * 256 + ((u & 8) | ((u ^ row) & 7)) * 16;
                    ldsm_x4(addr, a[mi]);
                }
                uint32_t b[4][4];
#pragma unroll
                for (int ni2 = 0; ni2 < 4; ni2++) {
                    int row = rBl + ni2 * 16;
                    int u = kc * 2 + hB;
                    uint32_t addr = Bb + row * 256 + ((u & 8) | ((u ^ row) & 7)) * 16;
                    ldsm_x4(addr, b[ni2]);
                }
#pragma unroll
                for (int mi = 0; mi < 2; mi++)
#pragma unroll
                    for (int ni = 0; ni < 8; ni++)
                        mma_bf16(c[mi][ni], a[mi], b[ni >> 1][(ni & 1) * 2],
                                 b[ni >> 1][(ni & 1) * 2 + 1]);
            }
        }

        // epilogue for this tile
        const int grow0 = job * 128 + mb + (l >> 2);
#pragma unroll
        for (int mi = 0; mi < 2; mi++) {
            float* r0 = Zb + (size_t)(grow0 + mi * 16) * GG;
            float* r1 = r0 + (size_t)8 * GG;
#pragma unroll
            for (int ni = 0; ni < 8; ni++) {
                float2 v0 = make_float2(c[mi][ni][0] + bs[ni].x, c[mi][ni][1] + bs[ni].y);
                float2 v1 = make_float2(c[mi][ni][2] + bs[ni].x, c[mi][ni][3] + bs[ni].y);
                *(float2*)(r0 + gcol0 + ni * 8) = v0;
                *(float2*)(r1 + gcol0 + ni * 8) = v1;
            }
        }

        __syncthreads();   // everyone done reading buffer cb before it is refilled
        cb ^= 1;
        job = nxt;
    }
}

// =====================================================================
// Phase 2: persistent recurrence — R2/R6 structure + HW tanh (R11, kept).
// =====================================================================
#define RECTHR 256
#define SMBLK  7
#define RPAIR  50

__global__ __launch_bounds__(RECTHR) void lstm_rec(
    const float* __restrict__ Wfw,
    const float* __restrict__ Wbw,
    float* __restrict__ out) {
    const int tid = threadIdx.x;
    const int j0  = tid;             // gate column A
    const int j1  = tid + 256;       // gate column B
    const int dir = blockIdx.x & 1;
    const int b   = blockIdx.x >> 1;
    const float* W  = dir ? Wbw : Wfw;
    const float* Wh = W + FF * GG;   // rows 128..255 = W_h

    extern __shared__ unsigned char sraw[];
    ulonglong2* ws = (ulonglong2*)sraw;                         // 7*512*16 = 57344 B
    float* zs   = (float*)(sraw + SMBLK * 512 * 16);            // 512 floats
    float* hbuf = (float*)(sraw + SMBLK * 512 * 16 + 2048);     // 128 floats, 16B aligned

    unsigned long long w0[2 * RPAIR];
    unsigned long long w1[2 * RPAIR];
#pragma unroll
    for (int p = 0; p < RPAIR; p++) {
        w0[p] = pk(Wh[(size_t)(2 * p) * GG + j0], Wh[(size_t)(2 * p + 1) * GG + j0]);
        w1[p] = pk(Wh[(size_t)(2 * p) * GG + j1], Wh[(size_t)(2 * p + 1) * GG + j1]);
    }
#pragma unroll
    for (int q = 0; q < SMBLK; q++) {
        int r = 100 + 4 * q;
        ulonglong2 vA, vB;
        vA.x = pk(Wh[(size_t)(r + 0) * GG + j0], Wh[(size_t)(r + 1) * GG + j0]);
        vA.y = pk(Wh[(size_t)(r + 2) * GG + j0], Wh[(size_t)(r + 3) * GG + j0]);
        vB.x = pk(Wh[(size_t)(r + 0) * GG + j1], Wh[(size_t)(r + 1) * GG + j1]);
        vB.y = pk(Wh[(size_t)(r + 2) * GG + j1], Wh[(size_t)(r + 3) * GG + j1]);
        ws[q * 512 + j0] = vA;
        ws[q * 512 + j1] = vB;
    }
    if (tid < UU) hbuf[tid] = 0.0f;
    float c = 0.0f;
    __syncthreads();

    const size_t base = ((size_t)dir * MM + (size_t)b * TT) * GG;
    const float* zp;
    long long zstep;
    int tt0;
    if (dir == 0) { zp = g_Z + base;                          zstep =  GG; tt0 = 0; }
    else          { zp = g_Z + base + (size_t)(TT - 1) * GG;  zstep = -GG; tt0 = TT - 1; }
    float zn0 = zp[j0], zn1 = zp[j1];

    float* outp = out + ((size_t)b * TT + tt0) * (2 * UU) + dir * UU + tid; // valid iff tid<128
    const long long ostep = (dir == 0) ? (2 * UU) : -(2 * UU);
    const int q4 = tid & 127;

    for (int t = 0; t < TT; t++) {
        float zc0 = zn0, zc1 = zn1;
        if (t + 1 < TT) { zp += zstep; zn0 = zp[j0]; zn1 = zp[j1]; }

        const ulonglong2* hb = (const ulonglong2*)hbuf;
        unsigned long long a00 = 0ull, a01 = 0ull, a10 = 0ull, a11 = 0ull;
#pragma unroll
        for (int p = 0; p < 25; p++) {
            ulonglong2 h2 = hb[p];
            a00 = fma2(w0[2 * p], h2.x, a00);
            a01 = fma2(w0[2 * p + 1], h2.y, a01);
            a10 = fma2(w1[2 * p], h2.x, a10);
            a11 = fma2(w1[2 * p + 1], h2.y, a11);
        }
#pragma unroll
        for (int qq = 0; qq < SMBLK; qq++) {
            ulonglong2 h2 = hb[25 + qq];
            ulonglong2 wA = ws[qq * 512 + j0];
            ulonglong2 wB = ws[qq * 512 + j1];
            a00 = fma2(wA.x, h2.x, a00);
            a01 = fma2(wA.y, h2.y, a01);
            a10 = fma2(wB.x, h2.x, a10);
            a11 = fma2(wB.y, h2.y, a11);
        }
        float2 s0 = upk(a00), s1 = upk(a01);
        float2 s2 = upk(a10), s3 = upk(a11);
        float z0 = (s0.x + s0.y) + (s1.x + s1.y) + zc0;
        float z1 = (s2.x + s2.y) + (s3.x + s3.y) + zc1;

        float act0, act1;
        if (tid < 128) { act0 = sigmA(z0);  act1 = sigmA(z1 + 1.0f); }
        else           { act0 = tanhA(z0);  act1 = sigmA(z1); }
        zs[j0] = act0;
        zs[j1] = act1;
        __syncthreads();

        float ai = zs[q4], aj = zs[q4 + 128], af = zs[q4 + 256], ao = zs[q4 + 384];
        c = fmaf(c, af, ai * aj);
        float h = ao * tanhA(c);
        if (tid < UU) {
            hbuf[tid] = h;
            *outp = h;
            outp += ostep;
        }
        __syncthreads();
    }
}

extern "C" void kernel_launch(void* const* d_in, const int* in_sizes, int n_in,
                              void* d_out, int out_size) {
    const float* x   = (const float*)d_in[0];
    const float* Wfw = (const float*)d_in[1];
    const float* bfw = (const float*)d_in[2];
    const float* Wbw = (const float*)d_in[3];
    const float* bbw = (const float*)d_in[4];
    float* out = (float*)d_out;

    cudaFuncSetAttribute(gemm_mma, cudaFuncAttributeMaxDynamicSharedMemorySize, 196608);
    const int recSmem = SMBLK * 512 * 16 + 2048 + 512;  // 59904
    cudaFuncSetAttribute(lstm_rec, cudaFuncAttributeMaxDynamicSharedMemorySize, recSmem);

    convert_x<<<8192, 256>>>(x);
    transpose_w<<<1024, 128>>>(Wfw, Wbw);
    dim3 gg(GMX, 4, 2);
    gemm_mma<<<gg, 256, 196608>>>(bfw, bbw);
    lstm_rec<<<128, RECTHR, recSmem>>>(Wfw, Wbw, out);
}